// round 15
// baseline (speedup 1.0000x reference)
#include <cuda_runtime.h>
#include <cuda_fp16.h>
#include <cstdint>

#define D_IN   64
#define D_OUT  64
#define D_HID  128
#define MAX_NODES 100000
#define NPB    128                 // nodes per block (M tile)
#define NT     256                 // threads per block (8 warps x 16 rows)
#define PREP_BLOCKS 65
#define EPT    16

// Scratch. g_deg: consume-reset invariant (zero at load; owning warp resets).
__device__ int   g_deg[MAX_NODES];
__device__ float g_bW[D_OUT];
// W12^T row-major [c][k], single fp16 (k contiguous).
__device__ __align__(16) unsigned short g_WT_h[D_OUT * D_IN];

// ---------------------------------------------------------------------------
__device__ __forceinline__ void mma_f16(float& d0, float& d1, float& d2, float& d3,
                                        uint32_t a0, uint32_t a1, uint32_t a2, uint32_t a3,
                                        uint32_t b0, uint32_t b1) {
    asm volatile(
        "mma.sync.aligned.m16n8k16.row.col.f32.f16.f16.f32 "
        "{%0,%1,%2,%3}, {%4,%5,%6,%7}, {%8,%9}, {%0,%1,%2,%3};"
        : "+f"(d0), "+f"(d1), "+f"(d2), "+f"(d3)
        : "r"(a0), "r"(a1), "r"(a2), "r"(a3), "r"(b0), "r"(b1));
}

// ---------------------------------------------------------------------------
// K1: blocks [0,65) -> W12^T fp16 + bW. Rest: degree histogram.
__global__ __launch_bounds__(256) void prep_hist_kernel(
    const int* __restrict__ ei32,
    const float* __restrict__ W1,
    const float* __restrict__ b1,
    const float* __restrict__ W2,
    int E)
{
    const int tid = threadIdx.x;

    if (blockIdx.x < PREP_BLOCKS) {
        const int r  = blockIdx.x;       // k index (or 64 => bW)
        const int j  = tid & 63;         // output column c
        const int kc = tid >> 6;
        const float* src = (r < D_IN) ? (W1 + (size_t)r * D_HID) : b1;

        float a = 0.f;
        #pragma unroll 8
        for (int k = kc * 32; k < kc * 32 + 32; ++k)
            a = fmaf(src[k], W2[(size_t)k * D_OUT + j], a);

        __shared__ float red[4][64];
        red[kc][j] = a;
        __syncthreads();
        if (kc == 0) {
            float v = red[0][j] + red[1][j] + red[2][j] + red[3][j];
            if (r < D_IN) {
                __half h = __float2half_rn(v);
                g_WT_h[j * D_IN + r] = *reinterpret_cast<unsigned short*>(&h);
            } else {
                g_bW[j] = v;
            }
        }
        return;
    }

    // ---- histogram over edge_index[1] (dst row), dtype self-detecting ----
    __shared__ int s_is64;
    if (tid == 0) {
        int is64 = 1;
        #pragma unroll
        for (int i = 1; i < 64; i += 2)
            if (ei32[i] != 0) is64 = 0;
        s_is64 = is64;
    }
    __syncthreads();

    const int hb = blockIdx.x - PREP_BLOCKS;
    const long long i0 = ((long long)hb * 256 + tid) * EPT;
    if (i0 >= E) return;

    if (s_is64) {
        const unsigned long long* p = (const unsigned long long*)ei32 + E;
        if (i0 + EPT <= E) {
            const ulonglong2* q = (const ulonglong2*)(p + i0);
            #pragma unroll
            for (int c = 0; c < EPT / 2; ++c) {
                ulonglong2 v = q[c];
                atomicAdd(&g_deg[(int)v.x], 1);
                atomicAdd(&g_deg[(int)v.y], 1);
            }
        } else {
            for (long long j = i0; j < E; ++j) atomicAdd(&g_deg[(int)p[j]], 1);
        }
    } else {
        const int* p = (const int*)ei32 + E;
        if (i0 + EPT <= E) {
            const int4* q = (const int4*)(p + i0);
            #pragma unroll
            for (int c = 0; c < EPT / 4; ++c) {
                int4 v = q[c];
                atomicAdd(&g_deg[v.x], 1); atomicAdd(&g_deg[v.y], 1);
                atomicAdd(&g_deg[v.z], 1); atomicAdd(&g_deg[v.w], 1);
            }
        } else {
            for (long long j = i0; j < E; ++j) atomicAdd(&g_deg[p[j]], 1);
        }
    }
}

// ---------------------------------------------------------------------------
// SMEM byte offsets (dynamic)
#define SM_BW  0                              // 64 f32
#define SM_B2  256                            // 64 f32
#define SM_WH  512                            // 64 x 144B
#define SM_XH  (SM_WH + 64 * 144)             // 128 x 144B (fp16)
#define SM_TOTAL (SM_XH + 128 * 144)          // 28160 B

// K2 (HMMA fp16): per block of 128 nodes, D = x_h @ W_h (fp32 acc),
//   out[n] = (1+deg)*(D[n] + bW) + b2.
// Warp-decoupled: one early barrier guards only W/biases; each warp stages
// its OWN 16 x-rows (nobody else reads them) and proceeds after __syncwarp.
// Degrees are read+reset by the owning warp (plain, no atomics) and
// distributed via shfl — no scale smem, no extra coupling.
__global__ __launch_bounds__(NT, 4) void gnn_mma_kernel(
    const float* __restrict__ x,
    const float* __restrict__ b2,
    float* __restrict__ out,
    int n)
{
    extern __shared__ char smem[];
    const int tid = threadIdx.x;
    const int wid = tid >> 5;
    const int lid = tid & 31;
    const int g   = lid >> 2;                  // 0..7
    const int t   = lid & 3;                   // 0..3
    const int base = blockIdx.x * NPB;
    const int wrow = wid * 16;                 // warp's first local row

    // Early degree read + consume-reset (warp-exclusive row ownership).
    int dreg = 0;
    if (lid < 16) {
        const int node = base + wrow + lid;
        if (node < n) { dreg = g_deg[node]; g_deg[node] = 0; }
    }

    // Stage W^T + biases (cooperative), then ONE block barrier.
    if (tid < D_OUT) {
        ((float*)(smem + SM_BW))[tid] = g_bW[tid];
        ((float*)(smem + SM_B2))[tid] = b2[tid];
    }
    #pragma unroll
    for (int it = 0; it < 4; ++it) {
        const int u = it * NT + tid;           // 0..1023
        const int c = u >> 4, q = u & 15;
        *(uint2*)(smem + SM_WH + c * 144 + q * 8) =
            *(const uint2*)((const char*)g_WT_h + c * 128 + q * 8);
    }
    __syncthreads();                           // guards W/bw/b2 only

    // Per-warp x staging: this warp's 16 rows, f32 -> fp16, padded rows.
    #pragma unroll
    for (int it = 0; it < 8; ++it) {
        const int u = it * 32 + lid;           // 0..255
        const int r16 = u >> 4, q4 = u & 15;   // row-in-warp, float4 idx
        const int row = wrow + r16;
        const int gr  = (base + row < n) ? (base + row) : (n - 1);
        const float4 v = ((const float4*)(x + (size_t)gr * D_IN))[q4];

        __half2 h0 = __float22half2_rn(make_float2(v.x, v.y));
        __half2 h1 = __float22half2_rn(make_float2(v.z, v.w));
        uint2 hv;
        hv.x = *reinterpret_cast<uint32_t*>(&h0);
        hv.y = *reinterpret_cast<uint32_t*>(&h1);
        *(uint2*)(smem + SM_XH + row * 144 + q4 * 8) = hv;
    }
    __syncwarp();                              // x rows are warp-private

    // ---- HMMA mainloop: warp owns rows [wrow, wrow+16) ----
    float acc[32];                             // 8 n-tiles x {d0,d1,d2,d3}
    #pragma unroll
    for (int i = 0; i < 32; ++i) acc[i] = 0.f;

    const uint32_t aoff = (uint32_t)((wrow + g) * 144 + 4 * t);
    const uint32_t boff = (uint32_t)(g * 144 + 4 * t);

    #pragma unroll
    for (int ks = 0; ks < 4; ++ks) {
        const uint32_t ak = aoff + ks * 32;
        const uint32_t a0 = *(const uint32_t*)(smem + SM_XH + ak);
        const uint32_t a1 = *(const uint32_t*)(smem + SM_XH + ak + 8 * 144);
        const uint32_t a2 = *(const uint32_t*)(smem + SM_XH + ak + 16);
        const uint32_t a3 = *(const uint32_t*)(smem + SM_XH + ak + 8 * 144 + 16);

        #pragma unroll
        for (int nt = 0; nt < 8; ++nt) {
            const uint32_t bk = boff + nt * 8 * 144 + ks * 32;
            const uint32_t b0 = *(const uint32_t*)(smem + SM_WH + bk);
            const uint32_t b1 = *(const uint32_t*)(smem + SM_WH + bk + 16);
            float* a = acc + nt * 4;
            mma_f16(a[0], a[1], a[2], a[3], a0, a1, a2, a3, b0, b1);
        }
    }

    // ---- Direct-from-fragment epilogue (scales via shfl) ----
    {
        const float* bw = (const float*)(smem + SM_BW);
        const float* bb = (const float*)(smem + SM_B2);
        const float s0 = 1.0f + (float)__shfl_sync(0xffffffffu, dreg, g);
        const float s1 = 1.0f + (float)__shfl_sync(0xffffffffu, dreg, g + 8);
        const int node0 = base + wrow + g;
        const int node1 = node0 + 8;
        const bool v0 = (node0 < n);
        const bool v1 = (node1 < n);
        float* op0 = out + (size_t)node0 * D_OUT;
        float* op1 = out + (size_t)node1 * D_OUT;

        #pragma unroll
        for (int nt = 0; nt < 8; ++nt) {
            const int c = nt * 8 + 2 * t;
            const float2 bwv = *(const float2*)(bw + c);
            const float2 bbv = *(const float2*)(bb + c);
            const float* a = acc + nt * 4;
            if (v0) {
                float2 r;
                r.x = fmaf(s0, a[0] + bwv.x, bbv.x);
                r.y = fmaf(s0, a[1] + bwv.y, bbv.y);
                *(float2*)(op0 + c) = r;
            }
            if (v1) {
                float2 r;
                r.x = fmaf(s1, a[2] + bwv.x, bbv.x);
                r.y = fmaf(s1, a[3] + bwv.y, bbv.y);
                *(float2*)(op1 + c) = r;
            }
        }
    }
}

// ---------------------------------------------------------------------------
extern "C" void kernel_launch(void* const* d_in, const int* in_sizes, int n_in,
                              void* d_out, int out_size) {
    const float* x  = (const float*)d_in[0];
    const void*  ei = d_in[1];
    const float* W1 = (const float*)d_in[2];
    const float* b1 = (const float*)d_in[3];
    const float* W2 = (const float*)d_in[4];
    const float* b2 = (const float*)d_in[5];
    float* out = (float*)d_out;

    const int n = in_sizes[0] / D_IN;   // 100000
    const int E = in_sizes[1] / 2;      // 1000000

    const int hist_blocks = (E + 256 * EPT - 1) / (256 * EPT);
    prep_hist_kernel<<<PREP_BLOCKS + hist_blocks, 256>>>(
        (const int*)ei, W1, b1, W2, E);

    cudaFuncSetAttribute(gnn_mma_kernel,
                         cudaFuncAttributeMaxDynamicSharedMemorySize, SM_TOTAL);
    gnn_mma_kernel<<<(n + NPB - 1) / NPB, NT, SM_TOTAL>>>(x, b2, out, n);
}